// round 4
// baseline (speedup 1.0000x reference)
#include <cuda_runtime.h>
#include <cstdint>

#define NN 50000
#define EE 800000
#define DD 128
#define GG 128
#define CC 10

// ---------------- static device scratch (no cudaMalloc allowed) ----------------
__device__ float g_buf[3][(size_t)NN * DD];   // feature buffers
__device__ int   g_cnt[NN];
__device__ int   g_rowptr[NN + 1];
__device__ int   g_cursor[NN];
__device__ int   g_src[EE];
__device__ float g_dinv[NN];
__device__ float g_sums[GG * DD];
__device__ float g_cntf[GG];

// ---------------- helpers ----------------
__device__ __forceinline__ uint32_t ftf32_u(float x) {
    uint32_t u;
    asm("cvt.rn.tf32.f32 %0, %1;" : "=r"(u) : "f"(x));
    return u;
}
__device__ __forceinline__ void mma_tf32(float c[4],
                                         uint32_t a0, uint32_t a1, uint32_t a2, uint32_t a3,
                                         uint32_t b0, uint32_t b1) {
    asm volatile(
        "mma.sync.aligned.m16n8k8.row.col.f32.tf32.tf32.f32 "
        "{%0,%1,%2,%3}, {%4,%5,%6,%7}, {%8,%9}, {%0,%1,%2,%3};"
        : "+f"(c[0]), "+f"(c[1]), "+f"(c[2]), "+f"(c[3])
        : "r"(a0), "r"(a1), "r"(a2), "r"(a3), "r"(b0), "r"(b1));
}

// ---------------- setup kernels ----------------
__global__ void k_zero() {
    int i = blockIdx.x * blockDim.x + threadIdx.x;
    if (i < NN) g_cnt[i] = 0;
    if (i < GG * DD) g_sums[i] = 0.f;
    if (i < GG) g_cntf[i] = 0.f;
}

__global__ void k_count(const int* __restrict__ col) {
    int e = blockIdx.x * blockDim.x + threadIdx.x;
    if (e < EE) atomicAdd(&g_cnt[col[e]], 1);
}

__global__ void k_scan() {
    __shared__ int partial[1024];
    const int T = 1024;
    int t = threadIdx.x;
    const int CH = (NN + T - 1) / T;
    int base = t * CH;
    int s = 0;
    for (int i = 0; i < CH; i++) {
        int idx = base + i;
        if (idx < NN) s += g_cnt[idx];
    }
    partial[t] = s;
    __syncthreads();
    for (int off = 1; off < T; off <<= 1) {
        int v = (t >= off) ? partial[t - off] : 0;
        __syncthreads();
        partial[t] += v;
        __syncthreads();
    }
    int run = (t == 0) ? 0 : partial[t - 1];
    for (int i = 0; i < CH; i++) {
        int idx = base + i;
        if (idx < NN) {
            g_rowptr[idx] = run;
            g_cursor[idx] = run;
            int c = g_cnt[idx];
            run += c;
            g_dinv[idx] = rsqrtf((float)c + 1.0f);
        }
    }
    if (t == T - 1) g_rowptr[NN] = partial[T - 1];
}

__global__ void k_fill(const int* __restrict__ row, const int* __restrict__ col) {
    int e = blockIdx.x * blockDim.x + threadIdx.x;
    if (e < EE) {
        int c = col[e];
        int p = atomicAdd(&g_cursor[c], 1);
        g_src[p] = row[e];
    }
}

// ---------------- gather kernels ----------------
__global__ void k_gather_x(const float* __restrict__ x) {
    int gw = (blockIdx.x * blockDim.x + threadIdx.x) >> 5;
    if (gw >= NN) return;
    int lane = threadIdx.x & 31;
    int beg = g_rowptr[gw], end = g_rowptr[gw + 1];
    float4 acc = make_float4(0.f, 0.f, 0.f, 0.f);
    int k = beg;
    for (; k + 4 <= end; k += 4) {
        int j0 = g_src[k], j1 = g_src[k + 1], j2 = g_src[k + 2], j3 = g_src[k + 3];
        float4 v0 = *(const float4*)&x[(size_t)j0 * DD + lane * 4];
        float4 v1 = *(const float4*)&x[(size_t)j1 * DD + lane * 4];
        float4 v2 = *(const float4*)&x[(size_t)j2 * DD + lane * 4];
        float4 v3 = *(const float4*)&x[(size_t)j3 * DD + lane * 4];
        acc.x += (v0.x + v1.x) + (v2.x + v3.x);
        acc.y += (v0.y + v1.y) + (v2.y + v3.y);
        acc.z += (v0.z + v1.z) + (v2.z + v3.z);
        acc.w += (v0.w + v1.w) + (v2.w + v3.w);
    }
    for (; k < end; k++) {
        int j = g_src[k];
        float4 v = *(const float4*)&x[(size_t)j * DD + lane * 4];
        acc.x += v.x; acc.y += v.y; acc.z += v.z; acc.w += v.w;
    }
    *(float4*)&g_buf[0][(size_t)gw * DD + lane * 4] = acc;
}

__global__ void k_gather_norm(int in_sel, int out_sel, const float* __restrict__ bias, int do_relu) {
    int gw = (blockIdx.x * blockDim.x + threadIdx.x) >> 5;
    if (gw >= NN) return;
    int lane = threadIdx.x & 31;
    const float* __restrict__ hps = g_buf[in_sel];
    int beg = g_rowptr[gw], end = g_rowptr[gw + 1];
    float4 acc = make_float4(0.f, 0.f, 0.f, 0.f);
    int k = beg;
    for (; k + 4 <= end; k += 4) {
        int j0 = g_src[k], j1 = g_src[k + 1], j2 = g_src[k + 2], j3 = g_src[k + 3];
        float4 v0 = *(const float4*)&hps[(size_t)j0 * DD + lane * 4];
        float4 v1 = *(const float4*)&hps[(size_t)j1 * DD + lane * 4];
        float4 v2 = *(const float4*)&hps[(size_t)j2 * DD + lane * 4];
        float4 v3 = *(const float4*)&hps[(size_t)j3 * DD + lane * 4];
        acc.x += (v0.x + v1.x) + (v2.x + v3.x);
        acc.y += (v0.y + v1.y) + (v2.y + v3.y);
        acc.z += (v0.z + v1.z) + (v2.z + v3.z);
        acc.w += (v0.w + v1.w) + (v2.w + v3.w);
    }
    for (; k < end; k++) {
        int j = g_src[k];
        float4 v = *(const float4*)&hps[(size_t)j * DD + lane * 4];
        acc.x += v.x; acc.y += v.y; acc.z += v.z; acc.w += v.w;
    }
    float4 self = *(const float4*)&hps[(size_t)gw * DD + lane * 4];
    float di = g_dinv[gw];
    float4 bb = *(const float4*)&bias[lane * 4];
    float4 o;
    o.x = di * (acc.x + self.x) + bb.x;
    o.y = di * (acc.y + self.y) + bb.y;
    o.z = di * (acc.z + self.z) + bb.z;
    o.w = di * (acc.w + self.w) + bb.w;
    if (do_relu) {
        o.x = fmaxf(o.x, 0.f); o.y = fmaxf(o.y, 0.f);
        o.z = fmaxf(o.z, 0.f); o.w = fmaxf(o.w, 0.f);
    }
    *(float4*)&g_buf[out_sel][(size_t)gw * DD + lane * 4] = o;
}

// ---------------- 3xTF32 mma.sync GEMM ----------------
// C[128 rows/block][128] = sum_p A_p @ W_p^T; epilogue (+bias)(relu)(×dinv) -> g_buf[out_sel]
// SMEM holds raw fp32: As[128][132], Ws[128][132]. hi/lo split at fragment-load time:
//   hi = tf32(v), lo = tf32(v - hi);  C += Ahi*Bhi + Alo*Bhi + Ahi*Blo  (fp32-class accuracy)
// 512 threads: 16 warps, warp tile 32x32 (wm=wid&3 m-strip, wn=wid>>2 n-strip).
#define GSMEM (2 * 128 * 132 * 4)
__global__ __launch_bounds__(512, 1) void k_gemm_mma(
    const float* __restrict__ x_ext,   // A1 for conv1 (P=2)
    int a0_sel,
    const float* __restrict__ W0,
    const float* __restrict__ W1,      // for P=2
    const float* __restrict__ bias,    // nullable
    int use_dinv, int relu, int P,
    int out_sel)
{
    extern __shared__ float sh[];
    float* As = sh;                 // 128*132
    float* Ws = sh + 128 * 132;

    int tid = threadIdx.x;
    int wid = tid >> 5, lane = tid & 31;
    int g = lane >> 2, t = lane & 3;
    int wm = wid & 3, wn = wid >> 2;     // warp tile: rows wm*32..+31, cols wn*32..+31
    int row0 = blockIdx.x * 128;

    float c[2][4][4];
#pragma unroll
    for (int ms = 0; ms < 2; ms++)
#pragma unroll
        for (int ns = 0; ns < 4; ns++)
#pragma unroll
            for (int j = 0; j < 4; j++) c[ms][ns][j] = 0.f;

    for (int p = 0; p < P; p++) {
        const float* Ap = p ? x_ext : g_buf[a0_sel];
        const float* Wp = p ? W1 : W0;
        // fill W (raw fp32)
        for (int idx = tid; idx < 4096; idx += 512) {
            int n = idx >> 5, k4 = idx & 31;
            *(float4*)&Ws[n * 132 + k4 * 4] = *(const float4*)&Wp[n * DD + k4 * 4];
        }
        // fill A (raw fp32)
        for (int idx = tid; idx < 4096; idx += 512) {
            int r = idx >> 5, k4 = idx & 31;
            int gr = row0 + r;
            float4 v = make_float4(0.f, 0.f, 0.f, 0.f);
            if (gr < NN) v = *(const float4*)&Ap[(size_t)gr * DD + k4 * 4];
            *(float4*)&As[r * 132 + k4 * 4] = v;
        }
        __syncthreads();

#pragma unroll 2
        for (int kk = 0; kk < 16; kk++) {
            // A fragments: 8 elements -> hi/lo
            uint32_t ahi[2][4], alo[2][4];
#pragma unroll
            for (int ms = 0; ms < 2; ms++) {
                const float* ap = &As[(wm * 32 + ms * 16 + g) * 132 + kk * 8 + t];
                float v0 = ap[0], v1 = ap[8 * 132], v2 = ap[4], v3 = ap[8 * 132 + 4];
                ahi[ms][0] = ftf32_u(v0); alo[ms][0] = ftf32_u(v0 - __uint_as_float(ahi[ms][0]));
                ahi[ms][1] = ftf32_u(v1); alo[ms][1] = ftf32_u(v1 - __uint_as_float(ahi[ms][1]));
                ahi[ms][2] = ftf32_u(v2); alo[ms][2] = ftf32_u(v2 - __uint_as_float(ahi[ms][2]));
                ahi[ms][3] = ftf32_u(v3); alo[ms][3] = ftf32_u(v3 - __uint_as_float(ahi[ms][3]));
            }
            // B fragments: 8 elements -> hi/lo
            uint32_t bhi[4][2], blo[4][2];
#pragma unroll
            for (int ns = 0; ns < 4; ns++) {
                const float* bp = &Ws[(wn * 32 + ns * 8 + g) * 132 + kk * 8 + t];
                float v0 = bp[0], v1 = bp[4];
                bhi[ns][0] = ftf32_u(v0); blo[ns][0] = ftf32_u(v0 - __uint_as_float(bhi[ns][0]));
                bhi[ns][1] = ftf32_u(v1); blo[ns][1] = ftf32_u(v1 - __uint_as_float(bhi[ns][1]));
            }
#pragma unroll
            for (int ms = 0; ms < 2; ms++)
#pragma unroll
                for (int ns = 0; ns < 4; ns++) {
                    mma_tf32(c[ms][ns], ahi[ms][0], ahi[ms][1], ahi[ms][2], ahi[ms][3],
                             bhi[ns][0], bhi[ns][1]);
                    mma_tf32(c[ms][ns], alo[ms][0], alo[ms][1], alo[ms][2], alo[ms][3],
                             bhi[ns][0], bhi[ns][1]);
                    mma_tf32(c[ms][ns], ahi[ms][0], ahi[ms][1], ahi[ms][2], ahi[ms][3],
                             blo[ns][0], blo[ns][1]);
                }
        }
        __syncthreads();
    }

    // epilogue
    float* out = g_buf[out_sel];
#pragma unroll
    for (int ms = 0; ms < 2; ms++) {
        int r_lo = row0 + wm * 32 + ms * 16 + g;
        int r_hi = r_lo + 8;
        float di_lo = 1.f, di_hi = 1.f;
        if (use_dinv) {
            if (r_lo < NN) di_lo = g_dinv[r_lo];
            if (r_hi < NN) di_hi = g_dinv[r_hi];
        }
#pragma unroll
        for (int ns = 0; ns < 4; ns++) {
            int col = wn * 32 + ns * 8 + 2 * t;
            float b0 = 0.f, b1 = 0.f;
            if (bias) { b0 = bias[col]; b1 = bias[col + 1]; }
            float f0 = c[ms][ns][0] + b0, f1 = c[ms][ns][1] + b1;
            float f2 = c[ms][ns][2] + b0, f3 = c[ms][ns][3] + b1;
            if (relu) {
                f0 = fmaxf(f0, 0.f); f1 = fmaxf(f1, 0.f);
                f2 = fmaxf(f2, 0.f); f3 = fmaxf(f3, 0.f);
            }
            if (r_lo < NN) *(float2*)&out[(size_t)r_lo * DD + col] = make_float2(f0 * di_lo, f1 * di_lo);
            if (r_hi < NN) *(float2*)&out[(size_t)r_hi * DD + col] = make_float2(f2 * di_hi, f3 * di_hi);
        }
    }
}

// ---------------- pooling ----------------
__global__ void k_pool(const int* __restrict__ batch, int sel) {
    const float* __restrict__ h = g_buf[sel];
    int start = blockIdx.x * 512;
    if (start >= NN) return;
    int endr = min(start + 512, NN);
    int d = threadIdx.x;
    int cur = batch[start];
    float run = 0.f, crun = 0.f;
    for (int r = start; r < endr; r++) {
        int b = batch[r];
        if (b != cur) {
            atomicAdd(&g_sums[cur * DD + d], run);
            if (d == 0) atomicAdd(&g_cntf[cur], crun);
            run = 0.f; crun = 0.f; cur = b;
        }
        run += h[(size_t)r * DD + d];
        crun += 1.f;
    }
    atomicAdd(&g_sums[cur * DD + d], run);
    if (d == 0) atomicAdd(&g_cntf[cur], crun);
}

// ---------------- finalize ----------------
__global__ void k_final(const float* __restrict__ Wl, const float* __restrict__ bl,
                        float* __restrict__ out)
{
    int g = blockIdx.x;
    int d = threadIdx.x;
    __shared__ float red[128];
    __shared__ float xsh[128];
    float c = g_cntf[g];
    float pooled = g_sums[g * DD + d] / fmaxf(c, 1.f);
    red[d] = pooled * pooled;
    __syncthreads();
    for (int s = 64; s > 0; s >>= 1) {
        if (d < s) red[d] += red[d + s];
        __syncthreads();
    }
    float inv = 1.f / fmaxf(sqrtf(red[0]), 1e-12f);
    float xn = pooled * inv;
    out[g * DD + d] = xn;
    xsh[d] = xn;
    __syncthreads();
    if (d < CC) {
        float dot = 0.f, w2 = 0.f;
        for (int k = 0; k < DD; k++) {
            float w = Wl[d * DD + k];
            dot += xsh[k] * w;
            w2 += w * w;
        }
        out[GG * DD + g * CC + d] = dot / fmaxf(sqrtf(w2), 1e-12f) + bl[d];
    }
}

// ---------------- launch ----------------
extern "C" void kernel_launch(void* const* d_in, const int* in_sizes, int n_in,
                              void* d_out, int out_size)
{
    const float* x   = (const float*)d_in[0];
    const int*   ei  = (const int*)d_in[1];
    const int*   bat = (const int*)d_in[2];
    const float* W1r = (const float*)d_in[3];
    const float* b1  = (const float*)d_in[4];
    const float* W1x = (const float*)d_in[5];
    const float* W2  = (const float*)d_in[6];
    const float* b2  = (const float*)d_in[7];
    const float* W3  = (const float*)d_in[8];
    const float* b3  = (const float*)d_in[9];
    const float* Wl  = (const float*)d_in[10];
    const float* bl  = (const float*)d_in[11];
    float* out = (float*)d_out;
    const int* row = ei;
    const int* col = ei + EE;

    cudaFuncSetAttribute(k_gemm_mma, cudaFuncAttributeMaxDynamicSharedMemorySize, GSMEM);

    int gwarps = (NN * 32 + 255) / 256;
    int tblocks = (NN + 127) / 128;

    k_zero<<<(NN + 255) / 256, 256>>>();
    k_count<<<(EE + 255) / 256, 256>>>(col);
    k_scan<<<1, 1024>>>();
    k_fill<<<(EE + 255) / 256, 256>>>(row, col);
    k_gather_x<<<gwarps, 256>>>(x);                              // buf0 = sum_nbr x

    // conv1: buf1 = relu(buf0 @ W1r^T + x @ W1x^T + b1)
    k_gemm_mma<<<tblocks, 512, GSMEM>>>(x, 0, W1r, W1x, b1, 0, 1, 2, 1);
    // buf0 = dinv * (buf1 @ W2^T)
    k_gemm_mma<<<tblocks, 512, GSMEM>>>(nullptr, 1, W2, nullptr, nullptr, 1, 0, 1, 0);
    k_gather_norm<<<gwarps, 256>>>(0, 2, b2, 1);                 // buf2 = h2
    // buf0 = dinv * (buf2 @ W3^T)
    k_gemm_mma<<<tblocks, 512, GSMEM>>>(nullptr, 2, W3, nullptr, nullptr, 1, 0, 1, 0);
    k_gather_norm<<<gwarps, 256>>>(0, 1, b3, 0);                 // buf1 = h3
    k_pool<<<(NN + 511) / 512, 128>>>(bat, 1);
    k_final<<<GG, 128>>>(Wl, bl, out);
}

// round 5
// speedup vs baseline: 1.1237x; 1.1237x over previous
#include <cuda_runtime.h>
#include <cuda_bf16.h>
#include <cstdint>

#define NN 50000
#define EE 800000
#define DD 128
#define GG 128
#define CC 10

// ---------------- static device scratch ----------------
__device__ float g_buf[3][(size_t)NN * DD];
__device__ int   g_cnt[NN];
__device__ int   g_rowptr[NN + 1];
__device__ int   g_cursor[NN];
__device__ int   g_src[EE];
__device__ float g_dinv[NN];
__device__ float g_sums[GG * DD];
__device__ float g_cntf[GG];

// ---------------- helpers ----------------
// pack split: hi bf16 in upper 16 bits, lo bf16 in lower 16 bits
__device__ __forceinline__ uint32_t pack_split(float v) {
    __nv_bfloat16 h = __float2bfloat16_rn(v);
    float hf = __bfloat162float(h);
    __nv_bfloat16 l = __float2bfloat16_rn(v - hf);
    return ((uint32_t)__bfloat16_as_ushort(h) << 16) | (uint32_t)__bfloat16_as_ushort(l);
}
__device__ __forceinline__ void mma_bf16(float c[4],
                                         uint32_t a0, uint32_t a1, uint32_t a2, uint32_t a3,
                                         uint32_t b0, uint32_t b1) {
    asm volatile(
        "mma.sync.aligned.m16n8k16.row.col.f32.bf16.bf16.f32 "
        "{%0,%1,%2,%3}, {%4,%5,%6,%7}, {%8,%9}, {%0,%1,%2,%3};"
        : "+f"(c[0]), "+f"(c[1]), "+f"(c[2]), "+f"(c[3])
        : "r"(a0), "r"(a1), "r"(a2), "r"(a3), "r"(b0), "r"(b1));
}
// word-column swizzle: conflict-free fragment LDS for rows sharing (r&3)
#define SWZ(r, c) ((c) ^ (((r) & 3) << 3))

// SMEM: As16[64][128] u32 (32KB) + Ws16[128][128] u32 (64KB) = 96KB
#define GS16 ((64 * 128 + 128 * 128) * 4)

// ---------------- setup kernels ----------------
__global__ void k_zero() {
    int i = blockIdx.x * blockDim.x + threadIdx.x;
    if (i < NN) g_cnt[i] = 0;
    if (i < GG * DD) g_sums[i] = 0.f;
    if (i < GG) g_cntf[i] = 0.f;
}

__global__ void k_count(const int* __restrict__ col, const int* __restrict__ batch) {
    int e = blockIdx.x * blockDim.x + threadIdx.x;
    if (e < EE) atomicAdd(&g_cnt[col[e]], 1);
    if (e < NN) atomicAdd(&g_cntf[batch[e]], 1.0f);
}

__global__ void k_scan() {
    __shared__ int partial[1024];
    const int T = 1024;
    int t = threadIdx.x;
    const int CH = (NN + T - 1) / T;
    int base = t * CH;
    int s = 0;
    for (int i = 0; i < CH; i++) {
        int idx = base + i;
        if (idx < NN) s += g_cnt[idx];
    }
    partial[t] = s;
    __syncthreads();
    for (int off = 1; off < T; off <<= 1) {
        int v = (t >= off) ? partial[t - off] : 0;
        __syncthreads();
        partial[t] += v;
        __syncthreads();
    }
    int run = (t == 0) ? 0 : partial[t - 1];
    for (int i = 0; i < CH; i++) {
        int idx = base + i;
        if (idx < NN) {
            g_rowptr[idx] = run;
            g_cursor[idx] = run;
            int c = g_cnt[idx];
            run += c;
            g_dinv[idx] = rsqrtf((float)c + 1.0f);
        }
    }
    if (t == T - 1) g_rowptr[NN] = partial[T - 1];
}

__global__ void k_fill(const int* __restrict__ row, const int* __restrict__ col) {
    int e = blockIdx.x * blockDim.x + threadIdx.x;
    if (e < EE) {
        int c = col[e];
        int p = atomicAdd(&g_cursor[c], 1);
        g_src[p] = row[e];
    }
}

// ---------------- shared GEMM pieces ----------------
// fill Ws16 from W[n][k] fp32 (row n = output col, k contiguous)
__device__ __forceinline__ void fill_W(uint32_t* Ws16, const float* __restrict__ W, int tid) {
    for (int idx = tid; idx < 4096; idx += 256) {
        int n = idx >> 5, c4 = idx & 31;
        float4 v = *(const float4*)&W[n * DD + c4 * 4];
        uint4 w;
        w.x = pack_split(v.x); w.y = pack_split(v.y);
        w.z = pack_split(v.z); w.w = pack_split(v.w);
        *(uint4*)&Ws16[n * 128 + SWZ(n, c4 * 4)] = w;
    }
}

// mainloop: 64x128x128, warp tile 32x32 (wm = wid&1, wn = wid>>1)
__device__ __forceinline__ void mma_main(const uint32_t* __restrict__ As16,
                                         const uint32_t* __restrict__ Ws16,
                                         float c[2][4][4], int wm, int wn, int g, int t) {
#pragma unroll
    for (int kk = 0; kk < 8; kk++) {
        int cA = kk * 16 + 2 * t;
        int cB = cA + 8;
        uint32_t ahi[2][4], alo[2][4];
#pragma unroll
        for (int ms = 0; ms < 2; ms++) {
            int r0 = wm * 32 + ms * 16 + g;
            int r1 = r0 + 8;
            uint2 w00 = *(const uint2*)&As16[r0 * 128 + SWZ(r0, cA)];
            uint2 w10 = *(const uint2*)&As16[r1 * 128 + SWZ(r1, cA)];
            uint2 w01 = *(const uint2*)&As16[r0 * 128 + SWZ(r0, cB)];
            uint2 w11 = *(const uint2*)&As16[r1 * 128 + SWZ(r1, cB)];
            ahi[ms][0] = __byte_perm(w00.x, w00.y, 0x7632); alo[ms][0] = __byte_perm(w00.x, w00.y, 0x5410);
            ahi[ms][1] = __byte_perm(w10.x, w10.y, 0x7632); alo[ms][1] = __byte_perm(w10.x, w10.y, 0x5410);
            ahi[ms][2] = __byte_perm(w01.x, w01.y, 0x7632); alo[ms][2] = __byte_perm(w01.x, w01.y, 0x5410);
            ahi[ms][3] = __byte_perm(w11.x, w11.y, 0x7632); alo[ms][3] = __byte_perm(w11.x, w11.y, 0x5410);
        }
        uint32_t bhi[4][2], blo[4][2];
#pragma unroll
        for (int ns = 0; ns < 4; ns++) {
            int n = wn * 32 + ns * 8 + g;
            uint2 w0 = *(const uint2*)&Ws16[n * 128 + SWZ(n, cA)];
            uint2 w1 = *(const uint2*)&Ws16[n * 128 + SWZ(n, cB)];
            bhi[ns][0] = __byte_perm(w0.x, w0.y, 0x7632); blo[ns][0] = __byte_perm(w0.x, w0.y, 0x5410);
            bhi[ns][1] = __byte_perm(w1.x, w1.y, 0x7632); blo[ns][1] = __byte_perm(w1.x, w1.y, 0x5410);
        }
        // three passes over tiles for C-dependency spacing
#pragma unroll
        for (int ms = 0; ms < 2; ms++)
#pragma unroll
            for (int ns = 0; ns < 4; ns++)
                mma_bf16(c[ms][ns], ahi[ms][0], ahi[ms][1], ahi[ms][2], ahi[ms][3], bhi[ns][0], bhi[ns][1]);
#pragma unroll
        for (int ms = 0; ms < 2; ms++)
#pragma unroll
            for (int ns = 0; ns < 4; ns++)
                mma_bf16(c[ms][ns], alo[ms][0], alo[ms][1], alo[ms][2], alo[ms][3], bhi[ns][0], bhi[ns][1]);
#pragma unroll
        for (int ms = 0; ms < 2; ms++)
#pragma unroll
            for (int ns = 0; ns < 4; ns++)
                mma_bf16(c[ms][ns], ahi[ms][0], ahi[ms][1], ahi[ms][2], ahi[ms][3], blo[ns][0], blo[ns][1]);
    }
}

// epilogue: +bias (opt), *dinv (opt) -> g_buf[out_sel]
__device__ __forceinline__ void epilogue(float c[2][4][4], int row0, int wm, int wn, int g, int t,
                                         const float* __restrict__ bias, int use_dinv, int out_sel) {
    float* out = g_buf[out_sel];
#pragma unroll
    for (int ms = 0; ms < 2; ms++) {
        int r_lo = row0 + wm * 32 + ms * 16 + g;
        int r_hi = r_lo + 8;
        float d_lo = 1.f, d_hi = 1.f;
        if (use_dinv) {
            if (r_lo < NN) d_lo = g_dinv[r_lo];
            if (r_hi < NN) d_hi = g_dinv[r_hi];
        }
#pragma unroll
        for (int ns = 0; ns < 4; ns++) {
            int col = wn * 32 + ns * 8 + 2 * t;
            float b0 = 0.f, b1 = 0.f;
            if (bias) { b0 = bias[col]; b1 = bias[col + 1]; }
            if (r_lo < NN)
                *(float2*)&out[(size_t)r_lo * DD + col] =
                    make_float2((c[ms][ns][0] + b0) * d_lo, (c[ms][ns][1] + b1) * d_lo);
            if (r_hi < NN)
                *(float2*)&out[(size_t)r_hi * DD + col] =
                    make_float2((c[ms][ns][2] + b0) * d_hi, (c[ms][ns][3] + b1) * d_hi);
        }
    }
}

// ---------------- plain GEMM from global A (for conv1 pre-passes) ----------------
__global__ __launch_bounds__(256, 2) void k_gemm_plain(
    const float* __restrict__ A, const float* __restrict__ W,
    const float* __restrict__ bias, int out_sel)
{
    extern __shared__ uint32_t sh16[];
    uint32_t* As16 = sh16;             // 64*128
    uint32_t* Ws16 = sh16 + 64 * 128;  // 128*128
    int tid = threadIdx.x;
    int wid = tid >> 5, lane = tid & 31;
    int g = lane >> 2, t = lane & 3;
    int wm = wid & 1, wn = wid >> 1;
    int row0 = blockIdx.x * 64;

    fill_W(Ws16, W, tid);
    for (int idx = tid; idx < 2048; idx += 256) {
        int r = idx >> 5, c4 = idx & 31;
        int gr = row0 + r;
        float4 v = make_float4(0.f, 0.f, 0.f, 0.f);
        if (gr < NN) v = *(const float4*)&A[(size_t)gr * DD + c4 * 4];
        uint4 w;
        w.x = pack_split(v.x); w.y = pack_split(v.y);
        w.z = pack_split(v.z); w.w = pack_split(v.w);
        *(uint4*)&As16[r * 128 + SWZ(r, c4 * 4)] = w;
    }
    __syncthreads();

    float c[2][4][4];
#pragma unroll
    for (int ms = 0; ms < 2; ms++)
#pragma unroll
        for (int ns = 0; ns < 4; ns++)
#pragma unroll
            for (int j = 0; j < 4; j++) c[ms][ns][j] = 0.f;
    mma_main(As16, Ws16, c, wm, wn, g, t);
    epilogue(c, row0, wm, wn, g, t, bias, 0, out_sel);
}

// ---------------- fused gather + GEMM ----------------
// gather phase: h_row = relu( csr_sum(in) [ +self, *dinv ] [+addArr_row] [+gbias] )
// then tile @ W^T, *dinv -> g_buf[out_sel]
__global__ __launch_bounds__(256, 2) void k_fused(
    int in_sel, int add_sel, int self_dinv,
    const float* __restrict__ gbias,
    const float* __restrict__ W, int out_sel)
{
    extern __shared__ uint32_t sh16[];
    uint32_t* As16 = sh16;
    uint32_t* Ws16 = sh16 + 64 * 128;
    int tid = threadIdx.x;
    int wid = tid >> 5, lane = tid & 31;
    int g = lane >> 2, t = lane & 3;
    int wm = wid & 1, wn = wid >> 1;
    int row0 = blockIdx.x * 64;

    fill_W(Ws16, W, tid);

    const float* __restrict__ hps = g_buf[in_sel];
    const float* __restrict__ addA = (add_sel >= 0) ? g_buf[add_sel] : nullptr;
    float4 bb = make_float4(0.f, 0.f, 0.f, 0.f);
    if (gbias) bb = *(const float4*)&gbias[lane * 4];

    // 8 warps x 8 rows
    for (int i = 0; i < 8; i++) {
        int r = wid * 8 + i;
        int gr = row0 + r;
        float4 o = make_float4(0.f, 0.f, 0.f, 0.f);
        if (gr < NN) {
            int beg = g_rowptr[gr], end = g_rowptr[gr + 1];
            float4 acc = make_float4(0.f, 0.f, 0.f, 0.f);
            int k = beg;
            for (; k + 4 <= end; k += 4) {
                int j0 = g_src[k], j1 = g_src[k + 1], j2 = g_src[k + 2], j3 = g_src[k + 3];
                float4 v0 = *(const float4*)&hps[(size_t)j0 * DD + lane * 4];
                float4 v1 = *(const float4*)&hps[(size_t)j1 * DD + lane * 4];
                float4 v2 = *(const float4*)&hps[(size_t)j2 * DD + lane * 4];
                float4 v3 = *(const float4*)&hps[(size_t)j3 * DD + lane * 4];
                acc.x += (v0.x + v1.x) + (v2.x + v3.x);
                acc.y += (v0.y + v1.y) + (v2.y + v3.y);
                acc.z += (v0.z + v1.z) + (v2.z + v3.z);
                acc.w += (v0.w + v1.w) + (v2.w + v3.w);
            }
            for (; k < end; k++) {
                int j = g_src[k];
                float4 v = *(const float4*)&hps[(size_t)j * DD + lane * 4];
                acc.x += v.x; acc.y += v.y; acc.z += v.z; acc.w += v.w;
            }
            if (self_dinv) {
                float4 self = *(const float4*)&hps[(size_t)gr * DD + lane * 4];
                float di = g_dinv[gr];
                acc.x = di * (acc.x + self.x);
                acc.y = di * (acc.y + self.y);
                acc.z = di * (acc.z + self.z);
                acc.w = di * (acc.w + self.w);
            }
            if (addA) {
                float4 av = *(const float4*)&addA[(size_t)gr * DD + lane * 4];
                acc.x += av.x; acc.y += av.y; acc.z += av.z; acc.w += av.w;
            }
            o.x = fmaxf(acc.x + bb.x, 0.f);
            o.y = fmaxf(acc.y + bb.y, 0.f);
            o.z = fmaxf(acc.z + bb.z, 0.f);
            o.w = fmaxf(acc.w + bb.w, 0.f);
        }
        uint4 w;
        w.x = pack_split(o.x); w.y = pack_split(o.y);
        w.z = pack_split(o.z); w.w = pack_split(o.w);
        *(uint4*)&As16[r * 128 + SWZ(r, lane * 4)] = w;
    }
    __syncthreads();

    float c[2][4][4];
#pragma unroll
    for (int ms = 0; ms < 2; ms++)
#pragma unroll
        for (int ns = 0; ns < 4; ns++)
#pragma unroll
            for (int j = 0; j < 4; j++) c[ms][ns][j] = 0.f;
    mma_main(As16, Ws16, c, wm, wn, g, t);
    epilogue(c, row0, wm, wn, g, t, nullptr, 1, out_sel);
}

// ---------------- final gather + pooling (run-accumulated atomics) ----------------
__global__ void k_gather_pool(const int* __restrict__ batch, const float* __restrict__ b3, int in_sel) {
    int w = (blockIdx.x * blockDim.x + threadIdx.x) >> 5;
    int r0 = w * 8;
    if (r0 >= NN) return;
    int lane = threadIdx.x & 31;
    const float* __restrict__ hps = g_buf[in_sel];
    float4 bb = *(const float4*)&b3[lane * 4];
    int r1 = min(r0 + 8, NN);
    int cur = batch[r0];
    float4 run = make_float4(0.f, 0.f, 0.f, 0.f);
    for (int r = r0; r < r1; r++) {
        int beg = g_rowptr[r], end = g_rowptr[r + 1];
        float4 acc = make_float4(0.f, 0.f, 0.f, 0.f);
        int k = beg;
        for (; k + 4 <= end; k += 4) {
            int j0 = g_src[k], j1 = g_src[k + 1], j2 = g_src[k + 2], j3 = g_src[k + 3];
            float4 v0 = *(const float4*)&hps[(size_t)j0 * DD + lane * 4];
            float4 v1 = *(const float4*)&hps[(size_t)j1 * DD + lane * 4];
            float4 v2 = *(const float4*)&hps[(size_t)j2 * DD + lane * 4];
            float4 v3 = *(const float4*)&hps[(size_t)j3 * DD + lane * 4];
            acc.x += (v0.x + v1.x) + (v2.x + v3.x);
            acc.y += (v0.y + v1.y) + (v2.y + v3.y);
            acc.z += (v0.z + v1.z) + (v2.z + v3.z);
            acc.w += (v0.w + v1.w) + (v2.w + v3.w);
        }
        for (; k < end; k++) {
            int j = g_src[k];
            float4 v = *(const float4*)&hps[(size_t)j * DD + lane * 4];
            acc.x += v.x; acc.y += v.y; acc.z += v.z; acc.w += v.w;
        }
        float4 self = *(const float4*)&hps[(size_t)r * DD + lane * 4];
        float di = g_dinv[r];
        float4 o;
        o.x = di * (acc.x + self.x) + bb.x;
        o.y = di * (acc.y + self.y) + bb.y;
        o.z = di * (acc.z + self.z) + bb.z;
        o.w = di * (acc.w + self.w) + bb.w;
        int b = batch[r];
        if (b != cur) {
            atomicAdd(&g_sums[cur * DD + lane * 4 + 0], run.x);
            atomicAdd(&g_sums[cur * DD + lane * 4 + 1], run.y);
            atomicAdd(&g_sums[cur * DD + lane * 4 + 2], run.z);
            atomicAdd(&g_sums[cur * DD + lane * 4 + 3], run.w);
            run = make_float4(0.f, 0.f, 0.f, 0.f);
            cur = b;
        }
        run.x += o.x; run.y += o.y; run.z += o.z; run.w += o.w;
    }
    atomicAdd(&g_sums[cur * DD + lane * 4 + 0], run.x);
    atomicAdd(&g_sums[cur * DD + lane * 4 + 1], run.y);
    atomicAdd(&g_sums[cur * DD + lane * 4 + 2], run.z);
    atomicAdd(&g_sums[cur * DD + lane * 4 + 3], run.w);
}

// ---------------- finalize ----------------
__global__ void k_final(const float* __restrict__ Wl, const float* __restrict__ bl,
                        float* __restrict__ out)
{
    int g = blockIdx.x;
    int d = threadIdx.x;
    __shared__ float red[128];
    __shared__ float xsh[128];
    float c = g_cntf[g];
    float pooled = g_sums[g * DD + d] / fmaxf(c, 1.f);
    red[d] = pooled * pooled;
    __syncthreads();
    for (int s = 64; s > 0; s >>= 1) {
        if (d < s) red[d] += red[d + s];
        __syncthreads();
    }
    float inv = 1.f / fmaxf(sqrtf(red[0]), 1e-12f);
    float xn = pooled * inv;
    out[g * DD + d] = xn;
    xsh[d] = xn;
    __syncthreads();
    if (d < CC) {
        float dot = 0.f, w2 = 0.f;
        for (int k = 0; k < DD; k++) {
            float w = Wl[d * DD + k];
            dot += xsh[k] * w;
            w2 += w * w;
        }
        out[GG * DD + g * CC + d] = dot / fmaxf(sqrtf(w2), 1e-12f) + bl[d];
    }
}

// ---------------- launch ----------------
extern "C" void kernel_launch(void* const* d_in, const int* in_sizes, int n_in,
                              void* d_out, int out_size)
{
    const float* x   = (const float*)d_in[0];
    const int*   ei  = (const int*)d_in[1];
    const int*   bat = (const int*)d_in[2];
    const float* W1r = (const float*)d_in[3];
    const float* b1  = (const float*)d_in[4];
    const float* W1x = (const float*)d_in[5];
    const float* W2  = (const float*)d_in[6];
    const float* b2  = (const float*)d_in[7];
    const float* W3  = (const float*)d_in[8];
    const float* b3  = (const float*)d_in[9];
    const float* Wl  = (const float*)d_in[10];
    const float* bl  = (const float*)d_in[11];
    float* out = (float*)d_out;
    const int* row = ei;
    const int* col = ei + EE;

    cudaFuncSetAttribute(k_gemm_plain, cudaFuncAttributeMaxDynamicSharedMemorySize, GS16);
    cudaFuncSetAttribute(k_fused, cudaFuncAttributeMaxDynamicSharedMemorySize, GS16);

    int tblocks = (NN + 63) / 64;   // 782

    k_zero<<<(NN + 255) / 256, 256>>>();
    k_count<<<(EE + 255) / 256, 256>>>(col, bat);
    k_scan<<<1, 1024>>>();
    k_fill<<<(EE + 255) / 256, 256>>>(row, col);

    // conv1 pre-GEMMs (by linearity of lin_rel over aggregation):
    k_gemm_plain<<<tblocks, 256, GS16>>>(x, W1r, nullptr, 0);   // buf0 = x @ W1r^T
    k_gemm_plain<<<tblocks, 256, GS16>>>(x, W1x, b1, 1);        // buf1 = x @ W1root^T + b1

    // F1: h1 = relu(agg(buf0) + buf1); t2 = dinv * (h1 @ W2^T) -> buf2
    k_fused<<<tblocks, 256, GS16>>>(0, 1, 0, nullptr, W2, 2);
    // F2: h2 = relu(dinv*(agg(buf2)+self) + b2); t3 = dinv * (h2 @ W3^T) -> buf0
    k_fused<<<tblocks, 256, GS16>>>(2, -1, 1, b2, W3, 0);
    // F3: h3 = dinv*(agg(buf0)+self) + b3, pooled directly into g_sums
    k_gather_pool<<<tblocks, 256>>>(bat, b3, 0);

    k_final<<<GG, 128>>>(Wl, bl, out);
}

// round 6
// speedup vs baseline: 1.1339x; 1.0091x over previous
#include <cuda_runtime.h>
#include <cuda_bf16.h>
#include <cstdint>

#define NN 50000
#define EE 800000
#define DD 128
#define GG 128
#define CC 10

// ---------------- static device scratch ----------------
__device__ float g_buf[3][(size_t)NN * DD];
__device__ int   g_cnt[NN];
__device__ int   g_rowptr[NN + 1];
__device__ int   g_cursor[NN];
__device__ int   g_src[EE];
__device__ float g_dinv[NN];
__device__ float g_sums[GG * DD];
__device__ float g_cntf[GG];

// ---------------- helpers ----------------
__device__ __forceinline__ uint32_t pack_split(float v) {
    __nv_bfloat16 h = __float2bfloat16_rn(v);
    float hf = __bfloat162float(h);
    __nv_bfloat16 l = __float2bfloat16_rn(v - hf);
    return ((uint32_t)__bfloat16_as_ushort(h) << 16) | (uint32_t)__bfloat16_as_ushort(l);
}
__device__ __forceinline__ void mma_bf16(float c[4],
                                         uint32_t a0, uint32_t a1, uint32_t a2, uint32_t a3,
                                         uint32_t b0, uint32_t b1) {
    asm volatile(
        "mma.sync.aligned.m16n8k16.row.col.f32.bf16.bf16.f32 "
        "{%0,%1,%2,%3}, {%4,%5,%6,%7}, {%8,%9}, {%0,%1,%2,%3};"
        : "+f"(c[0]), "+f"(c[1]), "+f"(c[2]), "+f"(c[3])
        : "r"(a0), "r"(a1), "r"(a2), "r"(a3), "r"(b0), "r"(b1));
}
#define SWZ(r, c) ((c) ^ (((r) & 3) << 3))

#define GS16  ((64 * 128 + 128 * 128) * 4)          // fused: A(32KB)+W(64KB)
#define GS16D ((64 * 128 + 256 * 128) * 4)          // dual:  A(32KB)+W(128KB)

// ---------------- setup kernels ----------------
__global__ void k_zero() {
    int i = blockIdx.x * blockDim.x + threadIdx.x;
    if (i < NN) g_cnt[i] = 0;
    if (i < GG * DD) g_sums[i] = 0.f;
    if (i < GG) g_cntf[i] = 0.f;
}

__global__ void k_count(const int* __restrict__ col, const int* __restrict__ batch) {
    int e = blockIdx.x * blockDim.x + threadIdx.x;
    if (e < EE) atomicAdd(&g_cnt[col[e]], 1);
    if (e < NN) atomicAdd(&g_cntf[batch[e]], 1.0f);
}

__global__ void k_scan() {
    __shared__ int partial[1024];
    const int T = 1024;
    int t = threadIdx.x;
    const int CH = (NN + T - 1) / T;
    int base = t * CH;
    int s = 0;
    for (int i = 0; i < CH; i++) {
        int idx = base + i;
        if (idx < NN) s += g_cnt[idx];
    }
    partial[t] = s;
    __syncthreads();
    for (int off = 1; off < T; off <<= 1) {
        int v = (t >= off) ? partial[t - off] : 0;
        __syncthreads();
        partial[t] += v;
        __syncthreads();
    }
    int run = (t == 0) ? 0 : partial[t - 1];
    for (int i = 0; i < CH; i++) {
        int idx = base + i;
        if (idx < NN) {
            g_rowptr[idx] = run;
            g_cursor[idx] = run;
            int c = g_cnt[idx];
            run += c;
            g_dinv[idx] = rsqrtf((float)c + 1.0f);
        }
    }
    if (t == T - 1) g_rowptr[NN] = partial[T - 1];
}

__global__ void k_fill(const int* __restrict__ row, const int* __restrict__ col) {
    int e = blockIdx.x * blockDim.x + threadIdx.x;
    if (e < EE) {
        int c = col[e];
        int p = atomicAdd(&g_cursor[c], 1);
        g_src[p] = row[e];
    }
}

// ---------------- dual conv1 pre-GEMM ----------------
// One pass over x: buf0 = x @ W1r^T ; buf1 = x @ W1x^T + b1
// SMEM: As16[64][128] + Ws16[256][128] (W' = [W1r ; W1x]) = 160KB, occupancy 1.
// 8 warps: wm=wid&1 (32-row strip), wn=wid>>1 (64-col strip of 256).
__global__ __launch_bounds__(256, 1) void k_gemm_dual(
    const float* __restrict__ A,
    const float* __restrict__ W1r, const float* __restrict__ W1x,
    const float* __restrict__ b1)
{
    extern __shared__ uint32_t sh16[];
    uint32_t* As16 = sh16;              // 64*128
    uint32_t* Ws16 = sh16 + 64 * 128;   // 256*128
    int tid = threadIdx.x;
    int wid = tid >> 5, lane = tid & 31;
    int g = lane >> 2, t = lane & 3;
    int wm = wid & 1, wn = wid >> 1;
    int row0 = blockIdx.x * 64;

    // fill W' (256 rows)
    for (int idx = tid; idx < 8192; idx += 256) {
        int n = idx >> 5, c4 = idx & 31;
        const float* Wp = (n < 128) ? &W1r[n * DD] : &W1x[(n - 128) * DD];
        float4 v = *(const float4*)&Wp[c4 * 4];
        uint4 w;
        w.x = pack_split(v.x); w.y = pack_split(v.y);
        w.z = pack_split(v.z); w.w = pack_split(v.w);
        *(uint4*)&Ws16[n * 128 + SWZ(n, c4 * 4)] = w;
    }
    // fill A
    for (int idx = tid; idx < 2048; idx += 256) {
        int r = idx >> 5, c4 = idx & 31;
        int gr = row0 + r;
        float4 v = make_float4(0.f, 0.f, 0.f, 0.f);
        if (gr < NN) v = *(const float4*)&A[(size_t)gr * DD + c4 * 4];
        uint4 w;
        w.x = pack_split(v.x); w.y = pack_split(v.y);
        w.z = pack_split(v.z); w.w = pack_split(v.w);
        *(uint4*)&As16[r * 128 + SWZ(r, c4 * 4)] = w;
    }
    __syncthreads();

    float c[2][8][4];
#pragma unroll
    for (int ms = 0; ms < 2; ms++)
#pragma unroll
        for (int ns = 0; ns < 8; ns++)
#pragma unroll
            for (int j = 0; j < 4; j++) c[ms][ns][j] = 0.f;

#pragma unroll 4
    for (int kk = 0; kk < 8; kk++) {
        int cA = kk * 16 + 2 * t;
        int cB = cA + 8;
        uint32_t ahi[2][4], alo[2][4];
#pragma unroll
        for (int ms = 0; ms < 2; ms++) {
            int r0 = wm * 32 + ms * 16 + g;
            int r1 = r0 + 8;
            uint2 w00 = *(const uint2*)&As16[r0 * 128 + SWZ(r0, cA)];
            uint2 w10 = *(const uint2*)&As16[r1 * 128 + SWZ(r1, cA)];
            uint2 w01 = *(const uint2*)&As16[r0 * 128 + SWZ(r0, cB)];
            uint2 w11 = *(const uint2*)&As16[r1 * 128 + SWZ(r1, cB)];
            ahi[ms][0] = __byte_perm(w00.x, w00.y, 0x7632); alo[ms][0] = __byte_perm(w00.x, w00.y, 0x5410);
            ahi[ms][1] = __byte_perm(w10.x, w10.y, 0x7632); alo[ms][1] = __byte_perm(w10.x, w10.y, 0x5410);
            ahi[ms][2] = __byte_perm(w01.x, w01.y, 0x7632); alo[ms][2] = __byte_perm(w01.x, w01.y, 0x5410);
            ahi[ms][3] = __byte_perm(w11.x, w11.y, 0x7632); alo[ms][3] = __byte_perm(w11.x, w11.y, 0x5410);
        }
#pragma unroll
        for (int ns = 0; ns < 8; ns++) {
            int n = wn * 64 + ns * 8 + g;
            uint2 w0 = *(const uint2*)&Ws16[n * 128 + SWZ(n, cA)];
            uint2 w1 = *(const uint2*)&Ws16[n * 128 + SWZ(n, cB)];
            uint32_t bhi0 = __byte_perm(w0.x, w0.y, 0x7632), blo0 = __byte_perm(w0.x, w0.y, 0x5410);
            uint32_t bhi1 = __byte_perm(w1.x, w1.y, 0x7632), blo1 = __byte_perm(w1.x, w1.y, 0x5410);
#pragma unroll
            for (int ms = 0; ms < 2; ms++) {
                mma_bf16(c[ms][ns], ahi[ms][0], ahi[ms][1], ahi[ms][2], ahi[ms][3], bhi0, bhi1);
                mma_bf16(c[ms][ns], alo[ms][0], alo[ms][1], alo[ms][2], alo[ms][3], bhi0, bhi1);
                mma_bf16(c[ms][ns], ahi[ms][0], ahi[ms][1], ahi[ms][2], ahi[ms][3], blo0, blo1);
            }
        }
    }

    // epilogue: cols [0,128) -> buf0 (no bias); cols [128,256) -> buf1 (+b1)
#pragma unroll
    for (int ms = 0; ms < 2; ms++) {
        int r_lo = row0 + wm * 32 + ms * 16 + g;
        int r_hi = r_lo + 8;
#pragma unroll
        for (int ns = 0; ns < 8; ns++) {
            int col = wn * 64 + ns * 8 + 2 * t;
            float* dst;
            float b0 = 0.f, b1v = 0.f;
            int cc = col;
            if (col < 128) dst = g_buf[0];
            else { dst = g_buf[1]; cc = col - 128; b0 = b1[cc]; b1v = b1[cc + 1]; }
            if (r_lo < NN)
                *(float2*)&dst[(size_t)r_lo * DD + cc] =
                    make_float2(c[ms][ns][0] + b0, c[ms][ns][1] + b1v);
            if (r_hi < NN)
                *(float2*)&dst[(size_t)r_hi * DD + cc] =
                    make_float2(c[ms][ns][2] + b0, c[ms][ns][3] + b1v);
        }
    }
}

// ---------------- fused gather + GEMM ----------------
__global__ __launch_bounds__(256, 2) void k_fused(
    int in_sel, int add_sel, int self_dinv,
    const float* __restrict__ gbias,
    const float* __restrict__ W, int out_sel)
{
    extern __shared__ uint32_t sh16[];
    uint32_t* As16 = sh16;
    uint32_t* Ws16 = sh16 + 64 * 128;
    int tid = threadIdx.x;
    int wid = tid >> 5, lane = tid & 31;
    int g = lane >> 2, t = lane & 3;
    int wm = wid & 1, wn = wid >> 1;
    int row0 = blockIdx.x * 64;

    for (int idx = tid; idx < 4096; idx += 256) {
        int n = idx >> 5, c4 = idx & 31;
        float4 v = *(const float4*)&W[n * DD + c4 * 4];
        uint4 w;
        w.x = pack_split(v.x); w.y = pack_split(v.y);
        w.z = pack_split(v.z); w.w = pack_split(v.w);
        *(uint4*)&Ws16[n * 128 + SWZ(n, c4 * 4)] = w;
    }

    const float* __restrict__ hps = g_buf[in_sel];
    const float* __restrict__ addA = (add_sel >= 0) ? g_buf[add_sel] : nullptr;
    float4 bb = make_float4(0.f, 0.f, 0.f, 0.f);
    if (gbias) bb = *(const float4*)&gbias[lane * 4];

    for (int i = 0; i < 8; i++) {
        int r = wid * 8 + i;
        int gr = row0 + r;
        float4 o = make_float4(0.f, 0.f, 0.f, 0.f);
        if (gr < NN) {
            int beg = g_rowptr[gr], end = g_rowptr[gr + 1];
            float4 acc = make_float4(0.f, 0.f, 0.f, 0.f);
            int k = beg;
            for (; k + 4 <= end; k += 4) {
                int j0 = g_src[k], j1 = g_src[k + 1], j2 = g_src[k + 2], j3 = g_src[k + 3];
                float4 v0 = *(const float4*)&hps[(size_t)j0 * DD + lane * 4];
                float4 v1 = *(const float4*)&hps[(size_t)j1 * DD + lane * 4];
                float4 v2 = *(const float4*)&hps[(size_t)j2 * DD + lane * 4];
                float4 v3 = *(const float4*)&hps[(size_t)j3 * DD + lane * 4];
                acc.x += (v0.x + v1.x) + (v2.x + v3.x);
                acc.y += (v0.y + v1.y) + (v2.y + v3.y);
                acc.z += (v0.z + v1.z) + (v2.z + v3.z);
                acc.w += (v0.w + v1.w) + (v2.w + v3.w);
            }
            for (; k < end; k++) {
                int j = g_src[k];
                float4 v = *(const float4*)&hps[(size_t)j * DD + lane * 4];
                acc.x += v.x; acc.y += v.y; acc.z += v.z; acc.w += v.w;
            }
            if (self_dinv) {
                float4 self = *(const float4*)&hps[(size_t)gr * DD + lane * 4];
                float di = g_dinv[gr];
                acc.x = di * (acc.x + self.x);
                acc.y = di * (acc.y + self.y);
                acc.z = di * (acc.z + self.z);
                acc.w = di * (acc.w + self.w);
            }
            if (addA) {
                float4 av = *(const float4*)&addA[(size_t)gr * DD + lane * 4];
                acc.x += av.x; acc.y += av.y; acc.z += av.z; acc.w += av.w;
            }
            o.x = fmaxf(acc.x + bb.x, 0.f);
            o.y = fmaxf(acc.y + bb.y, 0.f);
            o.z = fmaxf(acc.z + bb.z, 0.f);
            o.w = fmaxf(acc.w + bb.w, 0.f);
        }
        uint4 w;
        w.x = pack_split(o.x); w.y = pack_split(o.y);
        w.z = pack_split(o.z); w.w = pack_split(o.w);
        *(uint4*)&As16[r * 128 + SWZ(r, lane * 4)] = w;
    }
    __syncthreads();

    float c[2][4][4];
#pragma unroll
    for (int ms = 0; ms < 2; ms++)
#pragma unroll
        for (int ns = 0; ns < 4; ns++)
#pragma unroll
            for (int j = 0; j < 4; j++) c[ms][ns][j] = 0.f;

#pragma unroll
    for (int kk = 0; kk < 8; kk++) {
        int cA = kk * 16 + 2 * t;
        int cB = cA + 8;
        uint32_t ahi[2][4], alo[2][4];
#pragma unroll
        for (int ms = 0; ms < 2; ms++) {
            int r0 = wm * 32 + ms * 16 + g;
            int r1 = r0 + 8;
            uint2 w00 = *(const uint2*)&As16[r0 * 128 + SWZ(r0, cA)];
            uint2 w10 = *(const uint2*)&As16[r1 * 128 + SWZ(r1, cA)];
            uint2 w01 = *(const uint2*)&As16[r0 * 128 + SWZ(r0, cB)];
            uint2 w11 = *(const uint2*)&As16[r1 * 128 + SWZ(r1, cB)];
            ahi[ms][0] = __byte_perm(w00.x, w00.y, 0x7632); alo[ms][0] = __byte_perm(w00.x, w00.y, 0x5410);
            ahi[ms][1] = __byte_perm(w10.x, w10.y, 0x7632); alo[ms][1] = __byte_perm(w10.x, w10.y, 0x5410);
            ahi[ms][2] = __byte_perm(w01.x, w01.y, 0x7632); alo[ms][2] = __byte_perm(w01.x, w01.y, 0x5410);
            ahi[ms][3] = __byte_perm(w11.x, w11.y, 0x7632); alo[ms][3] = __byte_perm(w11.x, w11.y, 0x5410);
        }
        uint32_t bhi[4][2], blo[4][2];
#pragma unroll
        for (int ns = 0; ns < 4; ns++) {
            int n = wn * 32 + ns * 8 + g;
            uint2 w0 = *(const uint2*)&Ws16[n * 128 + SWZ(n, cA)];
            uint2 w1 = *(const uint2*)&Ws16[n * 128 + SWZ(n, cB)];
            bhi[ns][0] = __byte_perm(w0.x, w0.y, 0x7632); blo[ns][0] = __byte_perm(w0.x, w0.y, 0x5410);
            bhi[ns][1] = __byte_perm(w1.x, w1.y, 0x7632); blo[ns][1] = __byte_perm(w1.x, w1.y, 0x5410);
        }
#pragma unroll
        for (int ms = 0; ms < 2; ms++)
#pragma unroll
            for (int ns = 0; ns < 4; ns++)
                mma_bf16(c[ms][ns], ahi[ms][0], ahi[ms][1], ahi[ms][2], ahi[ms][3], bhi[ns][0], bhi[ns][1]);
#pragma unroll
        for (int ms = 0; ms < 2; ms++)
#pragma unroll
            for (int ns = 0; ns < 4; ns++)
                mma_bf16(c[ms][ns], alo[ms][0], alo[ms][1], alo[ms][2], alo[ms][3], bhi[ns][0], bhi[ns][1]);
#pragma unroll
        for (int ms = 0; ms < 2; ms++)
#pragma unroll
            for (int ns = 0; ns < 4; ns++)
                mma_bf16(c[ms][ns], ahi[ms][0], ahi[ms][1], ahi[ms][2], ahi[ms][3], blo[ns][0], blo[ns][1]);
    }

    float* out = g_buf[out_sel];
#pragma unroll
    for (int ms = 0; ms < 2; ms++) {
        int r_lo = row0 + wm * 32 + ms * 16 + g;
        int r_hi = r_lo + 8;
        float d_lo = 1.f, d_hi = 1.f;
        if (r_lo < NN) d_lo = g_dinv[r_lo];
        if (r_hi < NN) d_hi = g_dinv[r_hi];
#pragma unroll
        for (int ns = 0; ns < 4; ns++) {
            int col = wn * 32 + ns * 8 + 2 * t;
            if (r_lo < NN)
                *(float2*)&out[(size_t)r_lo * DD + col] =
                    make_float2(c[ms][ns][0] * d_lo, c[ms][ns][1] * d_lo);
            if (r_hi < NN)
                *(float2*)&out[(size_t)r_hi * DD + col] =
                    make_float2(c[ms][ns][2] * d_hi, c[ms][ns][3] * d_hi);
        }
    }
}

// ---------------- final gather + pooling ----------------
__global__ void k_gather_pool(const int* __restrict__ batch, const float* __restrict__ b3, int in_sel) {
    int w = (blockIdx.x * blockDim.x + threadIdx.x) >> 5;
    int r0 = w * 8;
    if (r0 >= NN) return;
    int lane = threadIdx.x & 31;
    const float* __restrict__ hps = g_buf[in_sel];
    float4 bb = *(const float4*)&b3[lane * 4];
    int r1 = min(r0 + 8, NN);
    int cur = batch[r0];
    float4 run = make_float4(0.f, 0.f, 0.f, 0.f);
    for (int r = r0; r < r1; r++) {
        int beg = g_rowptr[r], end = g_rowptr[r + 1];
        float4 acc = make_float4(0.f, 0.f, 0.f, 0.f);
        int k = beg;
        for (; k + 4 <= end; k += 4) {
            int j0 = g_src[k], j1 = g_src[k + 1], j2 = g_src[k + 2], j3 = g_src[k + 3];
            float4 v0 = *(const float4*)&hps[(size_t)j0 * DD + lane * 4];
            float4 v1 = *(const float4*)&hps[(size_t)j1 * DD + lane * 4];
            float4 v2 = *(const float4*)&hps[(size_t)j2 * DD + lane * 4];
            float4 v3 = *(const float4*)&hps[(size_t)j3 * DD + lane * 4];
            acc.x += (v0.x + v1.x) + (v2.x + v3.x);
            acc.y += (v0.y + v1.y) + (v2.y + v3.y);
            acc.z += (v0.z + v1.z) + (v2.z + v3.z);
            acc.w += (v0.w + v1.w) + (v2.w + v3.w);
        }
        for (; k < end; k++) {
            int j = g_src[k];
            float4 v = *(const float4*)&hps[(size_t)j * DD + lane * 4];
            acc.x += v.x; acc.y += v.y; acc.z += v.z; acc.w += v.w;
        }
        float4 self = *(const float4*)&hps[(size_t)r * DD + lane * 4];
        float di = g_dinv[r];
        float4 o;
        o.x = di * (acc.x + self.x) + bb.x;
        o.y = di * (acc.y + self.y) + bb.y;
        o.z = di * (acc.z + self.z) + bb.z;
        o.w = di * (acc.w + self.w) + bb.w;
        int b = batch[r];
        if (b != cur) {
            atomicAdd(&g_sums[cur * DD + lane * 4 + 0], run.x);
            atomicAdd(&g_sums[cur * DD + lane * 4 + 1], run.y);
            atomicAdd(&g_sums[cur * DD + lane * 4 + 2], run.z);
            atomicAdd(&g_sums[cur * DD + lane * 4 + 3], run.w);
            run = make_float4(0.f, 0.f, 0.f, 0.f);
            cur = b;
        }
        run.x += o.x; run.y += o.y; run.z += o.z; run.w += o.w;
    }
    atomicAdd(&g_sums[cur * DD + lane * 4 + 0], run.x);
    atomicAdd(&g_sums[cur * DD + lane * 4 + 1], run.y);
    atomicAdd(&g_sums[cur * DD + lane * 4 + 2], run.z);
    atomicAdd(&g_sums[cur * DD + lane * 4 + 3], run.w);
}

// ---------------- finalize ----------------
__global__ void k_final(const float* __restrict__ Wl, const float* __restrict__ bl,
                        float* __restrict__ out)
{
    int g = blockIdx.x;
    int d = threadIdx.x;
    __shared__ float red[128];
    __shared__ float xsh[128];
    float c = g_cntf[g];
    float pooled = g_sums[g * DD + d] / fmaxf(c, 1.f);
    red[d] = pooled * pooled;
    __syncthreads();
    for (int s = 64; s > 0; s >>= 1) {
        if (d < s) red[d] += red[d + s];
        __syncthreads();
    }
    float inv = 1.f / fmaxf(sqrtf(red[0]), 1e-12f);
    float xn = pooled * inv;
    out[g * DD + d] = xn;
    xsh[d] = xn;
    __syncthreads();
    if (d < CC) {
        float dot = 0.f, w2 = 0.f;
        for (int k = 0; k < DD; k++) {
            float w = Wl[d * DD + k];
            dot += xsh[k] * w;
            w2 += w * w;
        }
        out[GG * DD + g * CC + d] = dot / fmaxf(sqrtf(w2), 1e-12f) + bl[d];
    }
}

// ---------------- launch ----------------
extern "C" void kernel_launch(void* const* d_in, const int* in_sizes, int n_in,
                              void* d_out, int out_size)
{
    const float* x   = (const float*)d_in[0];
    const int*   ei  = (const int*)d_in[1];
    const int*   bat = (const int*)d_in[2];
    const float* W1r = (const float*)d_in[3];
    const float* b1  = (const float*)d_in[4];
    const float* W1x = (const float*)d_in[5];
    const float* W2  = (const float*)d_in[6];
    const float* b2  = (const float*)d_in[7];
    const float* W3  = (const float*)d_in[8];
    const float* b3  = (const float*)d_in[9];
    const float* Wl  = (const float*)d_in[10];
    const float* bl  = (const float*)d_in[11];
    float* out = (float*)d_out;
    const int* row = ei;
    const int* col = ei + EE;

    // one-time resource init (host-side; no device allocations)
    static cudaStream_t s2 = nullptr;
    static cudaEvent_t evFork = nullptr, evJoin = nullptr;
    if (s2 == nullptr) {
        cudaStreamCreateWithFlags(&s2, cudaStreamNonBlocking);
        cudaEventCreateWithFlags(&evFork, cudaEventDisableTiming);
        cudaEventCreateWithFlags(&evJoin, cudaEventDisableTiming);
    }

    cudaFuncSetAttribute(k_gemm_dual, cudaFuncAttributeMaxDynamicSharedMemorySize, GS16D);
    cudaFuncSetAttribute(k_fused, cudaFuncAttributeMaxDynamicSharedMemorySize, GS16);

    int tblocks = (NN + 63) / 64;   // 782

    // fork: branch B (s2) runs conv1 dual pre-GEMM concurrently with CSR build
    cudaEventRecord(evFork, 0);
    cudaStreamWaitEvent(s2, evFork, 0);
    k_gemm_dual<<<tblocks, 256, GS16D, s2>>>(x, W1r, W1x, b1);  // buf0 = x@W1r^T, buf1 = x@W1x^T + b1
    cudaEventRecord(evJoin, s2);

    // branch A (default stream): CSR build + zeros
    k_zero<<<(NN + 255) / 256, 256>>>();
    k_count<<<(EE + 255) / 256, 256>>>(col, bat);
    k_scan<<<1, 1024>>>();
    k_fill<<<(EE + 255) / 256, 256>>>(row, col);

    // join
    cudaStreamWaitEvent((cudaStream_t)0, evJoin, 0);

    // F1: h1 = relu(agg(buf0) + buf1); buf2 = dinv * (h1 @ W2^T)
    k_fused<<<tblocks, 256, GS16>>>(0, 1, 0, nullptr, W2, 2);
    // F2: h2 = relu(dinv*(agg(buf2)+self) + b2); buf0 = dinv * (h2 @ W3^T)
    k_fused<<<tblocks, 256, GS16>>>(2, -1, 1, b2, W3, 0);
    // F3: h3 = dinv*(agg(buf0)+self) + b3, pooled into g_sums
    k_gather_pool<<<tblocks, 256>>>(bat, b3, 0);

    k_final<<<GG, 128>>>(Wl, bl, out);
}